// round 3
// baseline (speedup 1.0000x reference)
#include <cuda_runtime.h>
#include <cuda_bf16.h>

// Problem collapse:
//   XR[b,n,:]   = R[tok[b,n], :]
//   A_unsc[b,n,m] = R[tok[b,n], tok[b,m]]
//   X_prime[b,n,v] = sum_{m<=n, tok[b,m]==v} softmax_m(A_unsc[b,n,:])
//   output = X_prime[:, N-1, :]  -> only last row, mask fully open.
//
// Per batch: gather 1024 scalars from one row of R, softmax over 1024,
// scatter-add probabilities into a 4096-entry histogram.

#define B 16
#define N 1024
#define V 4096

__global__ __launch_bounds__(N, 1)
void last_row_attn_kernel(const int* __restrict__ tok,
                          const float* __restrict__ R,
                          float* __restrict__ out) {
    __shared__ float acc[V];        // per-batch output histogram (16 KB)
    __shared__ float red_max[32];
    __shared__ float red_sum[32];

    const int b   = blockIdx.x;
    const int tid = threadIdx.x;
    const int* t  = tok + b * N;

    // zero the histogram (4 floats per thread)
    acc[tid]          = 0.0f;
    acc[tid + 1024]   = 0.0f;
    acc[tid + 2048]   = 0.0f;
    acc[tid + 3072]   = 0.0f;

    const int q  = t[N - 1];          // last-row query token (broadcast load)
    const int tm = t[tid];            // this thread's key token
    const float sc = R[(size_t)q * V + (size_t)tm];   // gathered score

    // ---- block max ----
    float m = sc;
    #pragma unroll
    for (int o = 16; o > 0; o >>= 1)
        m = fmaxf(m, __shfl_xor_sync(0xffffffffu, m, o));
    if ((tid & 31) == 0) red_max[tid >> 5] = m;
    __syncthreads();
    if (tid < 32) {
        float v = red_max[tid];
        #pragma unroll
        for (int o = 16; o > 0; o >>= 1)
            v = fmaxf(v, __shfl_xor_sync(0xffffffffu, v, o));
        red_max[tid] = v;
    }
    __syncthreads();
    const float mx = red_max[0];

    // ---- block sum of exp ----
    const float e = expf(sc - mx);
    float s = e;
    #pragma unroll
    for (int o = 16; o > 0; o >>= 1)
        s += __shfl_xor_sync(0xffffffffu, s, o);
    if ((tid & 31) == 0) red_sum[tid >> 5] = s;
    __syncthreads();
    if (tid < 32) {
        float v = red_sum[tid];
        #pragma unroll
        for (int o = 16; o > 0; o >>= 1)
            v += __shfl_xor_sync(0xffffffffu, v, o);
        red_sum[tid] = v;
    }
    __syncthreads();
    const float inv = 1.0f / red_sum[0];

    // ---- scatter-add probability into histogram ----
    atomicAdd(&acc[tm], e * inv);
    __syncthreads();

    // ---- coalesced write-out ----
    float* ob = out + (size_t)b * V;
    ob[tid]        = acc[tid];
    ob[tid + 1024] = acc[tid + 1024];
    ob[tid + 2048] = acc[tid + 2048];
    ob[tid + 3072] = acc[tid + 3072];
}

extern "C" void kernel_launch(void* const* d_in, const int* in_sizes, int n_in,
                              void* d_out, int out_size) {
    const int*   tok = (const int*)d_in[0];     // (16, 1024) int32
    const float* R   = (const float*)d_in[1];   // (4096, 4096) float32
    float*       out = (float*)d_out;           // (16, 4096) float32
    last_row_attn_kernel<<<B, N>>>(tok, R, out);
}